// round 7
// baseline (speedup 1.0000x reference)
#include <cuda_runtime.h>

#define GRID_H 13
#define GRID_W 13
#define NBOX   5
#define NELEM  85
#define NT     50
#define NTPAD  56
#define CPB    845            // cells per batch
#define NBATCH 256

#define NWARPS 8              // 256-thread blocks
#define CPW    4              // cells per warp (one per 8-lane group)
#define CELLS_PER_BLOCK (NWARPS * CPW)   // 32
#define NBLK_X 27
#define TOTAL_BLOCKS (NBLK_X * NBATCH)

#define FULL 0xFFFFFFFFu

__constant__ float c_anchors[10] = {
    0.57273f, 0.677385f, 1.87446f, 2.06253f, 3.33843f,
    5.47434f, 7.88282f, 3.52778f, 9.77052f, 9.16828f
};

// 5 accumulators on distinct L2 lines: 0 nb_coord, 1 nb_conf, 2 s_xywh, 3 s_conf, 4 s_class
__device__ float    g_acc[5 * 32];
__device__ unsigned g_done;

__device__ __forceinline__ float fast_sigmoid(float x) {
    return __fdividef(1.0f, 1.0f + __expf(-x));
}

__global__ __launch_bounds__(32 * NWARPS)
void yolo_loss_kernel(const float* __restrict__ y_true,
                      const float* __restrict__ y_pred,
                      const float* __restrict__ true_boxes,
                      float* __restrict__ out) {
    const int b    = blockIdx.y;
    const int warp = threadIdx.x >> 5;
    const int lane = threadIdx.x & 31;
    const int g    = lane >> 3;          // group = cell within warp
    const int s    = lane & 7;           // sublane within group

    // ---- shared: true-box extents (block-wide, one batch per block) ----
    __shared__ float4 s_ext[NTPAD];
    __shared__ float  s_b375[NTPAD];
    __shared__ float  s_part[NWARPS][6];

    if (threadIdx.x < NTPAD) {
        const int t = threadIdx.x;
        float4 v = (t < NT) ? ((const float4*)(true_boxes + b * NT * 4))[t]
                            : make_float4(1e9f, 0.f, 0.f, 0.f);
        s_ext[t]  = make_float4(v.x - v.z * 0.5f, v.x + v.z * 0.5f,
                                v.y - v.w * 0.5f, v.y + v.w * 0.5f);
        s_b375[t] = (t < NT) ? 0.375f * v.z * v.w : 3e38f;
    }
    __syncthreads();

    const int cellbase = blockIdx.x * CELLS_PER_BLOCK + warp * CPW;

    // ---- COALESCED class loads: e = lane + 32*i per cell (warp-contiguous, ~2 wf/req) ----
    float tpv[CPW][3], ttv[CPW][3];
    unsigned basek[CPW];
    #pragma unroll
    for (int k = 0; k < CPW; k++) {
        int cell = cellbase + k;
        if (cell >= CPB) cell = CPB - 1;
        const unsigned base = (unsigned)(b * CPB + cell) * NELEM;
        basek[k] = base;
        #pragma unroll
        for (int i = 0; i < 3; i++) {
            const int e = lane + 32 * i;
            const bool ok = (e < NELEM);
            tpv[k][i] = ok ? y_pred[base + e] : -1e30f;   // exp -> 0
            ttv[k][i] = ok ? y_true[base + e] : -1.0f;    // never wins argmax
        }
    }

    // ---- own-cell assignment (group g owns cell g) ----
    int cell_own = cellbase + g;
    const bool validc = (cell_own < CPB);
    if (!validc) cell_own = CPB - 1;
    const unsigned base_own = basek[0] + (unsigned)g * NELEM;  // == basek[g] (clamp only affects last block)
    const unsigned base_o   = (unsigned)(b * CPB + cell_own) * NELEM;

    // ---- box scalars: warp-broadcast loads (1 sector each, L1-resident lines) ----
    const float p0 = y_pred[base_o + 0], p1 = y_pred[base_o + 1];
    const float p2 = y_pred[base_o + 2], p3 = y_pred[base_o + 3];
    const float p4 = y_pred[base_o + 4];
    const float txo = y_true[base_o + 0], tyo = y_true[base_o + 1];
    const float two = y_true[base_o + 2], tho = y_true[base_o + 3];
    const float tco = y_true[base_o + 4];

    // ---- per-lane partial LSE for each cell (classes only: e >= 5) ----
    float v0[CPW];
    #pragma unroll
    for (int k = 0; k < CPW; k++) {
        const float c0val = (lane >= 5) ? tpv[k][0] : -1e30f;
        v0[k] = __expf(c0val) + __expf(tpv[k][1]) + __expf(tpv[k][2]);
    }
    // split-butterfly: converge to group ownership (lanes of group g hold cell g's sum)
    float se;
    {
        const bool hi16 = (lane & 16);
        float sendA = hi16 ? v0[0] : v0[2];
        float sendB = hi16 ? v0[1] : v0[3];
        const float rA = __shfl_xor_sync(FULL, sendA, 16);
        const float rB = __shfl_xor_sync(FULL, sendB, 16);
        const float x0 = (hi16 ? v0[2] : v0[0]) + rA;
        const float x1 = (hi16 ? v0[3] : v0[1]) + rB;
        const bool hi8 = (lane & 8);
        const float send = hi8 ? x0 : x1;
        const float r = __shfl_xor_sync(FULL, send, 8);
        se = (hi8 ? x1 : x0) + r;
        #pragma unroll
        for (int o = 4; o > 0; o >>= 1) se += __shfl_xor_sync(FULL, se, o);
    }

    // ---- per-lane partial argmax for each cell (first-max over classes) ----
    float av[CPW]; int ai[CPW];
    #pragma unroll
    for (int k = 0; k < CPW; k++) {
        float a = (lane >= 5) ? ttv[k][0] : -1.0f; int idx = lane;
        if (ttv[k][1] > a) { a = ttv[k][1]; idx = lane + 32; }
        if (ttv[k][2] > a) { a = ttv[k][2]; idx = lane + 64; }
        av[k] = a; ai[k] = idx;
    }
    int ai_o;   // argmax index for own cell
    {
        const bool hi16 = (lane & 16);
        float sA = hi16 ? av[0] : av[2]; int iA = hi16 ? ai[0] : ai[2];
        float sB = hi16 ? av[1] : av[3]; int iB = hi16 ? ai[1] : ai[3];
        const float rA = __shfl_xor_sync(FULL, sA, 16); const int jA = __shfl_xor_sync(FULL, iA, 16);
        const float rB = __shfl_xor_sync(FULL, sB, 16); const int jB = __shfl_xor_sync(FULL, iB, 16);
        float mA = hi16 ? av[2] : av[0]; int nA = hi16 ? ai[2] : ai[0];
        float mB = hi16 ? av[3] : av[1]; int nB = hi16 ? ai[3] : ai[1];
        if (rA > mA || (rA == mA && jA < nA)) { mA = rA; nA = jA; }
        if (rB > mB || (rB == mB && jB < nB)) { mB = rB; nB = jB; }
        const bool hi8 = (lane & 8);
        float sC = hi8 ? mA : mB; int iC = hi8 ? nA : nB;
        const float rC = __shfl_xor_sync(FULL, sC, 8); const int jC = __shfl_xor_sync(FULL, iC, 8);
        float m = hi8 ? mB : mA; int n = hi8 ? nB : nA;
        if (rC > m || (rC == m && jC < n)) { m = rC; n = jC; }
        #pragma unroll
        for (int o = 4; o > 0; o >>= 1) {
            const float r2 = __shfl_xor_sync(FULL, m, o);
            const int   j2 = __shfl_xor_sync(FULL, n, o);
            if (r2 > m || (r2 == m && j2 < n)) { m = r2; n = j2; }
        }
        ai_o = n;
    }

    // ---- predicted box (redundant within group: free in warp issue) ----
    const int boxo = cell_own % NBOX;
    const int wo   = (cell_own / NBOX) % GRID_W;
    const int ho   = cell_own / (NBOX * GRID_W);
    const float px = fast_sigmoid(p0) + (float)wo;
    const float py = fast_sigmoid(p1) + (float)ho;
    const float pw = __expf(p2) * c_anchors[2 * boxo];
    const float ph = __expf(p3) * c_anchors[2 * boxo + 1];
    const float pc = fast_sigmoid(p4);
    const float pxmin = px - pw * 0.5f, pxmax = px + pw * 0.5f;
    const float pymin = py - ph * 0.5f, pymax = py + ph * 0.5f;
    const float parea = pw * ph;
    const float p375  = 0.375f * parea;

    // ---- divisionless best-IoU >= 0.6 test: 7 boxes per sublane ----
    bool hit = false;
    #pragma unroll
    for (int j = 0; j < 7; j++) {
        const int t = s + 8 * j;
        const float4 e = s_ext[t];
        const float iw = fmaxf(fminf(pxmax, e.y) - fmaxf(pxmin, e.x), 0.0f);
        const float ih = fmaxf(fminf(pymax, e.w) - fmaxf(pymin, e.z), 0.0f);
        hit = hit || (iw * ih >= p375 + s_b375[t]);
    }
    const unsigned bal  = __ballot_sync(FULL, hit);
    const bool     hitg = ((bal >> (g * 8)) & 0xFFu) != 0u;

    // ---- epilogue ----
    const float lt = y_pred[base_o + ai_o];          // L1-hit broadcast
    const float ce = __logf(se) - lt;

    const float iw = fmaxf(fminf(pxmax, txo + two * 0.5f) - fmaxf(pxmin, txo - two * 0.5f), 0.0f);
    const float ih = fmaxf(fminf(pymax, tyo + tho * 0.5f) - fmaxf(pymin, tyo - tho * 0.5f), 0.0f);
    const float ia = iw * ih;
    const float iou = __fdividef(ia, parea + two * tho - ia);

    const float cm = tco;
    const float tc = iou * tco;
    const float fm = (hitg ? 0.0f : 1.0f) * (1.0f - tco) + 5.0f * tc;

    const float v = (validc && s == 0) ? 1.0f : 0.0f;
    float acc0 = v * ((cm > 0.0f) ? 1.0f : 0.0f);                        // nb_coord == nb_class
    float acc1 = v * ((fm > 0.0f) ? 1.0f : 0.0f);                        // nb_conf
    float acc2 = v * ((txo - px) * (txo - px) + (tyo - py) * (tyo - py)
                    + (two - pw) * (two - pw) + (tho - ph) * (tho - ph)) * cm;
    float acc3 = v * (tc - pc) * (tc - pc) * fm;
    float acc4 = v * ce * cm;

    #pragma unroll
    for (int o = 8; o < 32; o <<= 1) {
        acc0 += __shfl_xor_sync(FULL, acc0, o);
        acc1 += __shfl_xor_sync(FULL, acc1, o);
        acc2 += __shfl_xor_sync(FULL, acc2, o);
        acc3 += __shfl_xor_sync(FULL, acc3, o);
        acc4 += __shfl_xor_sync(FULL, acc4, o);
    }

    if (lane == 0) {
        s_part[warp][0] = acc0; s_part[warp][1] = acc1; s_part[warp][2] = acc2;
        s_part[warp][3] = acc3; s_part[warp][4] = acc4;
    }
    __syncthreads();
    if (warp == 0) {
        #pragma unroll
        for (int i = 0; i < 5; i++) {
            float t = (lane < NWARPS) ? s_part[lane][i] : 0.0f;
            #pragma unroll
            for (int o = 4; o > 0; o >>= 1) t += __shfl_down_sync(FULL, t, o);
            if (lane == 0) atomicAdd(&g_acc[i * 32], t);
        }
    }

    // ---- last-block finalize (single launch) ----
    if (threadIdx.x == 0) {
        __threadfence();
        const unsigned t = atomicAdd(&g_done, 1u);
        if (t == (unsigned)(TOTAL_BLOCKS - 1)) {
            __threadfence();
            float a[5];
            #pragma unroll
            for (int i = 0; i < 5; i++) a[i] = atomicAdd(&g_acc[i * 32], 0.0f);
            const float nbc = a[0] + 1e-6f;
            const float nbf = a[1] + 1e-6f;
            out[0] = a[2] / nbc * 0.5f
                   + a[3] / nbf * 0.5f
                   + a[4] / nbc;
            #pragma unroll
            for (int i = 0; i < 5; i++) g_acc[i * 32] = 0.0f;
            g_done = 0u;
        }
    }
}

extern "C" void kernel_launch(void* const* d_in, const int* in_sizes, int n_in,
                              void* d_out, int out_size) {
    const float* y_true     = (const float*)d_in[0];
    const float* y_pred     = (const float*)d_in[1];
    const float* true_boxes = (const float*)d_in[2];
    float* out = (float*)d_out;

    dim3 grid(NBLK_X, NBATCH);
    yolo_loss_kernel<<<grid, 32 * NWARPS>>>(y_true, y_pred, true_boxes, out);
}

// round 8
// speedup vs baseline: 1.0688x; 1.0688x over previous
#include <cuda_runtime.h>

#define GRID_H 13
#define GRID_W 13
#define NBOX   5
#define NELEM  85
#define NT     50
#define NTPAD  56
#define CPB    845            // cells per batch
#define NBATCH 256

#define NWARPS 8              // 256-thread blocks
#define CPW    4              // cells per warp (one per 8-lane group)
#define CSTRIDE 88            // padded cell stride in staging (conflict-free: 88%32=24)
#define CELLS_PER_BLOCK (NWARPS * CPW)   // 32
#define NBLK_X 27
#define TOTAL_BLOCKS (NBLK_X * NBATCH)

#define FULL 0xFFFFFFFFu

__constant__ float c_anchors[10] = {
    0.57273f, 0.677385f, 1.87446f, 2.06253f, 3.33843f,
    5.47434f, 7.88282f, 3.52778f, 9.77052f, 9.16828f
};

// 5 accumulators on distinct L2 lines: 0 nb_coord, 1 nb_conf, 2 s_xywh, 3 s_conf, 4 s_class
__device__ float    g_acc[5 * 32];
__device__ unsigned g_done;

__device__ __forceinline__ float fast_sigmoid(float x) {
    return __fdividef(1.0f, 1.0f + __expf(-x));
}

__global__ __launch_bounds__(32 * NWARPS)
void yolo_loss_kernel(const float* __restrict__ y_true,
                      const float* __restrict__ y_pred,
                      const float* __restrict__ true_boxes,
                      float* __restrict__ out) {
    const int b    = blockIdx.y;
    const int warp = threadIdx.x >> 5;
    const int lane = threadIdx.x & 31;
    const int g    = lane >> 3;          // group = cell within warp
    const int s    = lane & 7;           // sublane within group

    // ---- shared ----
    __shared__ float  s_stage[NWARPS][2][CPW * CSTRIDE];   // [warp][pred/true][cell*88+e]
    __shared__ float4 s_ext[NTPAD];
    __shared__ float  s_b375[NTPAD];
    __shared__ float  s_part[NWARPS][6];

    if (threadIdx.x < NTPAD) {
        const int t = threadIdx.x;
        float4 v = (t < NT) ? ((const float4*)(true_boxes + b * NT * 4))[t]
                            : make_float4(1e9f, 0.f, 0.f, 0.f);
        s_ext[t]  = make_float4(v.x - v.z * 0.5f, v.x + v.z * 0.5f,
                                v.y - v.w * 0.5f, v.y + v.w * 0.5f);
        s_b375[t] = (t < NT) ? 0.375f * v.z * v.w : 3e38f;
    }
    __syncthreads();

    const int cellbase = blockIdx.x * CELLS_PER_BLOCK + warp * CPW;
    float* stp = s_stage[warp][0];
    float* stt = s_stage[warp][1];

    // ---- coalesced LDG -> conflict-free STS staging (warp-private) ----
    #pragma unroll
    for (int k = 0; k < CPW; k++) {
        int cell = cellbase + k;
        if (cell >= CPB) cell = CPB - 1;
        const unsigned base = (unsigned)(b * CPB + cell) * NELEM;
        #pragma unroll
        for (int i = 0; i < 3; i++) {
            const int e = lane + 32 * i;
            if (e < NELEM) {
                stp[k * CSTRIDE + e] = y_pred[base + e];
                stt[k * CSTRIDE + e] = y_true[base + e];
            }
        }
    }
    __syncwarp();

    // ---- own-cell assignment (group g owns cell g) ----
    int cell_own = cellbase + g;
    const bool validc = (cell_own < CPB);
    if (!validc) cell_own = CPB - 1;

    // ---- box scalars from staging (broadcast LDS, conflict-free across groups) ----
    const int gb = g * CSTRIDE;
    const float p0 = stp[gb + 0], p1 = stp[gb + 1], p2 = stp[gb + 2],
                p3 = stp[gb + 3], p4 = stp[gb + 4];
    const float txo = stt[gb + 0], tyo = stt[gb + 1];
    const float two = stt[gb + 2], tho = stt[gb + 3];
    const float tco = stt[gb + 4];

    // ---- classes: e = 5 + s + 8i (exactly [5,85), no predication, conflict-free LDS) ----
    float se = 0.0f;
    float av = -1.0f; int ai = 0x7FFFFFFF;
    #pragma unroll
    for (int i = 0; i < 10; i++) {
        const int e = 5 + s + 8 * i;
        se += __expf(stp[gb + e]);
        const float tte = stt[gb + e];
        if (tte > av) { av = tte; ai = e; }
    }
    // intra-group butterflies (3 steps)
    #pragma unroll
    for (int o = 1; o < 8; o <<= 1) se += __shfl_xor_sync(FULL, se, o);
    #pragma unroll
    for (int o = 1; o < 8; o <<= 1) {
        const float v2 = __shfl_xor_sync(FULL, av, o);
        const int   i2 = __shfl_xor_sync(FULL, ai, o);
        if (v2 > av || (v2 == av && i2 < ai)) { av = v2; ai = i2; }
    }

    // ---- predicted box (redundant within group: free in warp issue) ----
    const int boxo = cell_own % NBOX;
    const int wo   = (cell_own / NBOX) % GRID_W;
    const int ho   = cell_own / (NBOX * GRID_W);
    const float px = fast_sigmoid(p0) + (float)wo;
    const float py = fast_sigmoid(p1) + (float)ho;
    const float pw = __expf(p2) * c_anchors[2 * boxo];
    const float ph = __expf(p3) * c_anchors[2 * boxo + 1];
    const float pc = fast_sigmoid(p4);
    const float pxmin = px - pw * 0.5f, pxmax = px + pw * 0.5f;
    const float pymin = py - ph * 0.5f, pymax = py + ph * 0.5f;
    const float parea = pw * ph;
    const float p375  = 0.375f * parea;

    // ---- divisionless best-IoU >= 0.6 test: 7 boxes per sublane ----
    bool hit = false;
    #pragma unroll
    for (int j = 0; j < 7; j++) {
        const int t = s + 8 * j;
        const float4 e = s_ext[t];
        const float iw = fmaxf(fminf(pxmax, e.y) - fmaxf(pxmin, e.x), 0.0f);
        const float ih = fmaxf(fminf(pymax, e.w) - fmaxf(pymin, e.z), 0.0f);
        hit = hit || (iw * ih >= p375 + s_b375[t]);
    }
    const unsigned bal  = __ballot_sync(FULL, hit);
    const bool     hitg = ((bal >> (g * 8)) & 0xFFu) != 0u;

    // ---- epilogue ----
    const float lt = stp[gb + ai];               // LDS broadcast (ai uniform in group)
    const float ce = __logf(se) - lt;

    const float iw = fmaxf(fminf(pxmax, txo + two * 0.5f) - fmaxf(pxmin, txo - two * 0.5f), 0.0f);
    const float ih = fmaxf(fminf(pymax, tyo + tho * 0.5f) - fmaxf(pymin, tyo - tho * 0.5f), 0.0f);
    const float ia = iw * ih;
    const float iou = __fdividef(ia, parea + two * tho - ia);

    const float cm = tco;                        // coord mask == class mask
    const float tc = iou * tco;
    const float fm = (hitg ? 0.0f : 1.0f) * (1.0f - tco) + 5.0f * tc;

    const float v = (validc && s == 0) ? 1.0f : 0.0f;
    float acc0 = v * ((cm > 0.0f) ? 1.0f : 0.0f);                        // nb_coord == nb_class
    float acc1 = v * ((fm > 0.0f) ? 1.0f : 0.0f);                        // nb_conf
    float acc2 = v * ((txo - px) * (txo - px) + (tyo - py) * (tyo - py)
                    + (two - pw) * (two - pw) + (tho - ph) * (tho - ph)) * cm;  // s_xy+s_wh
    float acc3 = v * (tc - pc) * (tc - pc) * fm;                         // s_conf
    float acc4 = v * ce * cm;                                            // s_class

    // ---- reduce group leaders -> lane 0 ----
    #pragma unroll
    for (int o = 8; o < 32; o <<= 1) {
        acc0 += __shfl_xor_sync(FULL, acc0, o);
        acc1 += __shfl_xor_sync(FULL, acc1, o);
        acc2 += __shfl_xor_sync(FULL, acc2, o);
        acc3 += __shfl_xor_sync(FULL, acc3, o);
        acc4 += __shfl_xor_sync(FULL, acc4, o);
    }

    if (lane == 0) {
        s_part[warp][0] = acc0; s_part[warp][1] = acc1; s_part[warp][2] = acc2;
        s_part[warp][3] = acc3; s_part[warp][4] = acc4;
    }
    __syncthreads();
    if (warp == 0) {
        #pragma unroll
        for (int i = 0; i < 5; i++) {
            float t = (lane < NWARPS) ? s_part[lane][i] : 0.0f;
            #pragma unroll
            for (int o = 4; o > 0; o >>= 1) t += __shfl_down_sync(FULL, t, o);
            if (lane == 0) atomicAdd(&g_acc[i * 32], t);
        }
    }

    // ---- last-block finalize (single launch) ----
    if (threadIdx.x == 0) {
        __threadfence();
        const unsigned t = atomicAdd(&g_done, 1u);
        if (t == (unsigned)(TOTAL_BLOCKS - 1)) {
            __threadfence();
            float a[5];
            #pragma unroll
            for (int i = 0; i < 5; i++) a[i] = atomicAdd(&g_acc[i * 32], 0.0f);
            const float nbc = a[0] + 1e-6f;
            const float nbf = a[1] + 1e-6f;
            out[0] = a[2] / nbc * 0.5f          // loss_xy + loss_wh
                   + a[3] / nbf * 0.5f          // loss_conf
                   + a[4] / nbc;                // loss_class (nb_class == nb_coord)
            #pragma unroll
            for (int i = 0; i < 5; i++) g_acc[i * 32] = 0.0f;
            g_done = 0u;
        }
    }
}

extern "C" void kernel_launch(void* const* d_in, const int* in_sizes, int n_in,
                              void* d_out, int out_size) {
    const float* y_true     = (const float*)d_in[0];
    const float* y_pred     = (const float*)d_in[1];
    const float* true_boxes = (const float*)d_in[2];
    float* out = (float*)d_out;

    dim3 grid(NBLK_X, NBATCH);
    yolo_loss_kernel<<<grid, 32 * NWARPS>>>(y_true, y_pred, true_boxes, out);
}